// round 1
// baseline (speedup 1.0000x reference)
#include <cuda_runtime.h>
#include <math.h>

#define NN 100000
#define EE 3200000
#define DD 256
#define LN_EPS 1e-5f

// ---------------- scratch (static device globals: no allocation) ----------------
__device__ float g_h[(size_t)NN * DD];    // layer-1 output / layer-2 residual
__device__ float g_xw[(size_t)NN * DD];   // h @ W
__device__ float g_agg[(size_t)NN * DD];  // aggregated messages
__device__ float g_deg[NN];
__device__ float g_dis[NN];
__device__ int   g_idx64;                 // 1 if edge_index is int64, 0 if int32

__device__ __forceinline__ float fsafe(float v) { return isfinite(v) ? v : 0.0f; }

__device__ __forceinline__ int load_idx(const void* base, long long e) {
    if (g_idx64) return (int)((const long long*)base)[e];
    return ((const int*)base)[e];
}

// ---------------- edge-index dtype detection ----------------
__global__ void detect_idx_kernel(const void* ei) {
    // If data is int32, reading pairs as int64 gives v0 + v1*2^32 with v1 usually
    // nonzero -> huge values. If int64, all values are in [0, NN).
    if (threadIdx.x == 0 && blockIdx.x == 0) {
        const long long* p = (const long long*)ei;
        int ok64 = 1;
        for (int i = 0; i < 1024; i++) {
            long long v = p[i];
            if (v < 0 || v >= NN) { ok64 = 0; break; }
        }
        g_idx64 = ok64;
    }
}

// ---------------- degree / dis ----------------
__global__ void zero_deg_kernel() {
    int i = blockIdx.x * blockDim.x + threadIdx.x;
    if (i < NN) g_deg[i] = 0.0f;
}

__global__ void deg_accum_kernel(const void* __restrict__ ei, const float* __restrict__ ew) {
    int e = blockIdx.x * blockDim.x + threadIdx.x;
    if (e < EE) {
        float w = fmaxf(fabsf(fsafe(ew[e])), 1e-6f);
        int c = load_idx(ei, (long long)EE + e);
        atomicAdd(&g_deg[c], w);
    }
}

__global__ void dis_kernel() {
    int i = blockIdx.x * blockDim.x + threadIdx.x;
    if (i < NN) g_dis[i] = rsqrtf(g_deg[i] + 1.0f);
}

// ---------------- SGEMM: g_xw = safe(A) @ W  (A: [NN,256], W: [256,256]) ----------------
// 128x128 block tile, BK=8, 256 threads, 8x8 per-thread micro-tile.
__global__ void sgemm_kernel(const float* __restrict__ Aext, int a_from_h,
                             const float* __restrict__ W) {
    __shared__ float As[8][128];
    __shared__ float Bs[8][128];
    const float* A = a_from_h ? g_h : Aext;

    const int tid = threadIdx.x;
    const int m0 = blockIdx.y * 128;
    const int n0 = blockIdx.x * 128;
    const int tx = tid & 15;       // N direction, 16 threads
    const int ty = tid >> 4;       // M direction, 16 threads
    const int arow = tid >> 1;     // 0..127
    const int acol = (tid & 1) * 4;
    const int brow = tid >> 5;     // 0..7
    const int bcol = (tid & 31) * 4;

    float acc[8][8];
#pragma unroll
    for (int i = 0; i < 8; i++)
#pragma unroll
        for (int j = 0; j < 8; j++) acc[i][j] = 0.0f;

    const int garow = m0 + arow;
    for (int k0 = 0; k0 < DD; k0 += 8) {
        float4 av = make_float4(0.f, 0.f, 0.f, 0.f);
        if (garow < NN) av = *(const float4*)&A[(size_t)garow * DD + k0 + acol];
        As[acol + 0][arow] = fsafe(av.x);
        As[acol + 1][arow] = fsafe(av.y);
        As[acol + 2][arow] = fsafe(av.z);
        As[acol + 3][arow] = fsafe(av.w);
        float4 bv = *(const float4*)&W[(size_t)(k0 + brow) * DD + n0 + bcol];
        *(float4*)&Bs[brow][bcol] = bv;
        __syncthreads();
#pragma unroll
        for (int k = 0; k < 8; k++) {
            float ar[8], br[8];
#pragma unroll
            for (int i = 0; i < 8; i++) ar[i] = As[k][ty * 8 + i];
#pragma unroll
            for (int j = 0; j < 8; j++) br[j] = Bs[k][tx * 8 + j];
#pragma unroll
            for (int i = 0; i < 8; i++)
#pragma unroll
                for (int j = 0; j < 8; j++) acc[i][j] += ar[i] * br[j];
        }
        __syncthreads();
    }
#pragma unroll
    for (int i = 0; i < 8; i++) {
        int r = m0 + ty * 8 + i;
        if (r < NN) {
#pragma unroll
            for (int j = 0; j < 8; j += 4) {
                float4 v = make_float4(acc[i][j], acc[i][j + 1], acc[i][j + 2], acc[i][j + 3]);
                *(float4*)&g_xw[(size_t)r * DD + n0 + tx * 8 + j] = v;
            }
        }
    }
}

// ---------------- self-loop init: agg[i] = dis[i]^2 * xw[i] ----------------
__global__ void selfloop_kernel() {
    size_t idx = (size_t)blockIdx.x * blockDim.x + threadIdx.x;  // float4 index
    if (idx >= (size_t)NN * (DD / 4)) return;
    int node = (int)(idx >> 6);
    float s = g_dis[node];
    s = s * s;
    float4 v = ((const float4*)g_xw)[idx];
    v.x *= s; v.y *= s; v.z *= s; v.w *= s;
    ((float4*)g_agg)[idx] = v;
}

// ---------------- edge scatter: agg[col] += norm * xw[row] ----------------
// One warp per edge; each lane handles 2 float4 (8 floats).
__global__ void edge_kernel(const void* __restrict__ ei, const float* __restrict__ ew) {
    int gw = (int)(((size_t)blockIdx.x * blockDim.x + threadIdx.x) >> 5);
    int lane = threadIdx.x & 31;
    if (gw >= EE) return;
    int r = load_idx(ei, gw);
    int c = load_idx(ei, (long long)EE + gw);
    float w = fmaxf(fabsf(fsafe(__ldg(&ew[gw]))), 1e-6f);
    float norm = g_dis[r] * w * g_dis[c];
    const float4* src = (const float4*)(g_xw + (size_t)r * DD);
    float4* dst = (float4*)(g_agg + (size_t)c * DD);
#pragma unroll
    for (int i = 0; i < 2; i++) {
        float4 v = __ldg(&src[lane + i * 32]);
        v.x *= norm; v.y *= norm; v.z *= norm; v.w *= norm;
        float4* p = dst + lane + i * 32;
        asm volatile("red.global.add.v4.f32 [%0], {%1,%2,%3,%4};"
                     :: "l"(p), "f"(v.x), "f"(v.y), "f"(v.z), "f"(v.w)
                     : "memory");
    }
}

// ---------------- post: bias + LN + relu + residual ----------------
// One warp per node.
__global__ void post_kernel(const float* __restrict__ bias, const float* __restrict__ gam,
                            const float* __restrict__ bet,
                            const float* __restrict__ hres_ext, int res_from_h,
                            float* __restrict__ out_ext, int out_to_h) {
    int node = (int)(((size_t)blockIdx.x * blockDim.x + threadIdx.x) >> 5);
    int lane = threadIdx.x & 31;
    if (node >= NN) return;
    const float* hres = res_from_h ? g_h : hres_ext;
    float* out = out_to_h ? g_h : out_ext;

    const float4* ag = (const float4*)(g_agg + (size_t)node * DD);
    float4 a0 = ag[lane], a1 = ag[lane + 32];
    float4 b0 = ((const float4*)bias)[lane], b1 = ((const float4*)bias)[lane + 32];

    float v[8];
    v[0] = fsafe(a0.x + b0.x); v[1] = fsafe(a0.y + b0.y);
    v[2] = fsafe(a0.z + b0.z); v[3] = fsafe(a0.w + b0.w);
    v[4] = fsafe(a1.x + b1.x); v[5] = fsafe(a1.y + b1.y);
    v[6] = fsafe(a1.z + b1.z); v[7] = fsafe(a1.w + b1.w);

    float s = 0.f;
#pragma unroll
    for (int i = 0; i < 8; i++) s += v[i];
#pragma unroll
    for (int o = 16; o; o >>= 1) s += __shfl_xor_sync(0xffffffffu, s, o);
    float mu = s * (1.0f / DD);

    float vs = 0.f;
#pragma unroll
    for (int i = 0; i < 8; i++) { float d = v[i] - mu; vs += d * d; }
#pragma unroll
    for (int o = 16; o; o >>= 1) vs += __shfl_xor_sync(0xffffffffu, vs, o);
    float inv = rsqrtf(vs * (1.0f / DD) + LN_EPS);

    float4 g0 = ((const float4*)gam)[lane], g1 = ((const float4*)gam)[lane + 32];
    float4 e0 = ((const float4*)bet)[lane], e1 = ((const float4*)bet)[lane + 32];
    const float4* hr = (const float4*)(hres + (size_t)node * DD);
    float4 h0 = hr[lane], h1 = hr[lane + 32];

    float gg[8] = {g0.x, g0.y, g0.z, g0.w, g1.x, g1.y, g1.z, g1.w};
    float bb[8] = {e0.x, e0.y, e0.z, e0.w, e1.x, e1.y, e1.z, e1.w};
    float hh[8] = {h0.x, h0.y, h0.z, h0.w, h1.x, h1.y, h1.z, h1.w};

    float o_[8];
#pragma unroll
    for (int i = 0; i < 8; i++) {
        float y = (v[i] - mu) * inv * gg[i] + bb[i];
        y = fmaxf(fsafe(y), 0.0f);          // safe(LN) then relu
        o_[i] = fsafe(y + fsafe(hh[i]));    // residual (+ safes)
    }
    float4* op = (float4*)(out + (size_t)node * DD);
    op[lane]      = make_float4(o_[0], o_[1], o_[2], o_[3]);
    op[lane + 32] = make_float4(o_[4], o_[5], o_[6], o_[7]);
}

// ---------------- launch ----------------
extern "C" void kernel_launch(void* const* d_in, const int* in_sizes, int n_in,
                              void* d_out, int out_size) {
    const float* x   = (const float*)d_in[0];
    const void*  ei  = d_in[1];            // edge_index [2, E] (int32 or int64, detected)
    const float* ew  = (const float*)d_in[2];
    const float* W1  = (const float*)d_in[3];
    const float* b1  = (const float*)d_in[4];
    const float* g1  = (const float*)d_in[5];
    const float* be1 = (const float*)d_in[6];
    const float* W2  = (const float*)d_in[7];
    const float* b2  = (const float*)d_in[8];
    const float* g2  = (const float*)d_in[9];
    const float* be2 = (const float*)d_in[10];
    float* out = (float*)d_out;

    detect_idx_kernel<<<1, 32>>>(ei);

    zero_deg_kernel<<<(NN + 255) / 256, 256>>>();
    deg_accum_kernel<<<(EE + 255) / 256, 256>>>(ei, ew);
    dis_kernel<<<(NN + 255) / 256, 256>>>();

    dim3 gemm_grid(DD / 128, (NN + 127) / 128);
    int selfloop_blocks = (int)(((size_t)NN * (DD / 4) + 255) / 256);
    int edge_blocks = (int)(((size_t)EE * 32 + 255) / 256);
    int post_blocks = (int)(((size_t)NN * 32 + 255) / 256);

    // ---- layer 1 ----
    sgemm_kernel<<<gemm_grid, 256>>>(x, 0, W1);
    selfloop_kernel<<<selfloop_blocks, 256>>>();
    edge_kernel<<<edge_blocks, 256>>>(ei, ew);
    post_kernel<<<post_blocks, 256>>>(b1, g1, be1, x, 0, nullptr, 1);   // -> g_h

    // ---- layer 2 ----
    sgemm_kernel<<<gemm_grid, 256>>>(nullptr, 1, W2);
    selfloop_kernel<<<selfloop_blocks, 256>>>();
    edge_kernel<<<edge_blocks, 256>>>(ei, ew);
    post_kernel<<<post_blocks, 256>>>(b2, g2, be2, nullptr, 1, out, 0); // -> d_out
}

// round 2
// speedup vs baseline: 1.7967x; 1.7967x over previous
#include <cuda_runtime.h>
#include <math.h>

#define NN 100000
#define EE 3200000
#define DD 256
#define LN_EPS 1e-5f
#define SCAN_B 1024
#define NB ((NN + SCAN_B - 1) / SCAN_B)

// ---------------- scratch (static device globals: no allocation) ----------------
__device__ float g_h[(size_t)NN * DD];    // layer-1 output / layer-2 residual
__device__ float g_xw[(size_t)NN * DD];   // h @ W
__device__ float g_deg[NN];
__device__ float g_dis[NN];
__device__ int   g_cnt[NN];               // in-degree (edge count) per dst
__device__ int   g_off[NN];               // CSR offsets (exclusive scan of cnt)
__device__ int   g_cur[NN];               // fill cursors
__device__ int   g_bsum[NB];              // scan block partials
__device__ int   g_esrc[EE];              // CSR: source node per slot
__device__ float g_enrm[EE];              // CSR: edge norm per slot
__device__ int   g_idx64;                 // 1 if edge_index is int64

__device__ __forceinline__ float fsafe(float v) { return isfinite(v) ? v : 0.0f; }

__device__ __forceinline__ int load_idx(const void* base, long long e) {
    if (g_idx64) return (int)((const long long*)base)[e];
    return ((const int*)base)[e];
}

// ---------------- edge-index dtype detection ----------------
__global__ void detect_idx_kernel(const void* ei) {
    if (threadIdx.x == 0 && blockIdx.x == 0) {
        const long long* p = (const long long*)ei;
        int ok64 = 1;
        for (int i = 0; i < 1024; i++) {
            long long v = p[i];
            if (v < 0 || v >= NN) { ok64 = 0; break; }
        }
        g_idx64 = ok64;
    }
}

// ---------------- CSR build ----------------
__global__ void zero_kernel() {
    int i = blockIdx.x * blockDim.x + threadIdx.x;
    if (i < NN) { g_deg[i] = 0.0f; g_cnt[i] = 0; }
}

__global__ void count_kernel(const void* __restrict__ ei, const float* __restrict__ ew) {
    int e = blockIdx.x * blockDim.x + threadIdx.x;
    if (e < EE) {
        float w = fmaxf(fabsf(fsafe(ew[e])), 1e-6f);
        int c = load_idx(ei, (long long)EE + e);
        atomicAdd(&g_deg[c], w);
        atomicAdd(&g_cnt[c], 1);
    }
}

__global__ void dis_kernel() {
    int i = blockIdx.x * blockDim.x + threadIdx.x;
    if (i < NN) g_dis[i] = rsqrtf(g_deg[i] + 1.0f);
}

__global__ void scan1_kernel() {
    __shared__ int s[SCAN_B];
    int tid = threadIdx.x;
    int i = blockIdx.x * SCAN_B + tid;
    int v = (i < NN) ? g_cnt[i] : 0;
    s[tid] = v;
    __syncthreads();
#pragma unroll
    for (int o = 1; o < SCAN_B; o <<= 1) {
        int t = (tid >= o) ? s[tid - o] : 0;
        __syncthreads();
        s[tid] += t;
        __syncthreads();
    }
    if (i < NN) g_off[i] = s[tid] - v;     // exclusive within block
    if (tid == SCAN_B - 1) g_bsum[blockIdx.x] = s[tid];
}

__global__ void scan2_kernel() {
    if (threadIdx.x == 0 && blockIdx.x == 0) {
        int run = 0;
        for (int b = 0; b < NB; b++) { int t = g_bsum[b]; g_bsum[b] = run; run += t; }
    }
}

__global__ void scan3_kernel() {
    int i = blockIdx.x * SCAN_B + threadIdx.x;
    if (i < NN) {
        int o = g_off[i] + g_bsum[blockIdx.x];
        g_off[i] = o;
        g_cur[i] = o;
    }
}

__global__ void fill_kernel(const void* __restrict__ ei, const float* __restrict__ ew) {
    int e = blockIdx.x * blockDim.x + threadIdx.x;
    if (e < EE) {
        int r = load_idx(ei, e);
        int c = load_idx(ei, (long long)EE + e);
        float w = fmaxf(fabsf(fsafe(ew[e])), 1e-6f);
        float norm = g_dis[r] * w * g_dis[c];
        int pos = atomicAdd(&g_cur[c], 1);
        g_esrc[pos] = r;
        g_enrm[pos] = norm;
    }
}

// ---------------- SGEMM: g_xw = safe(A) @ W ----------------
__global__ void sgemm_kernel(const float* __restrict__ Aext, int a_from_h,
                             const float* __restrict__ W) {
    __shared__ float As[8][128];
    __shared__ float Bs[8][128];
    const float* A = a_from_h ? g_h : Aext;

    const int tid = threadIdx.x;
    const int m0 = blockIdx.y * 128;
    const int n0 = blockIdx.x * 128;
    const int tx = tid & 15;
    const int ty = tid >> 4;
    const int arow = tid >> 1;
    const int acol = (tid & 1) * 4;
    const int brow = tid >> 5;
    const int bcol = (tid & 31) * 4;

    float acc[8][8];
#pragma unroll
    for (int i = 0; i < 8; i++)
#pragma unroll
        for (int j = 0; j < 8; j++) acc[i][j] = 0.0f;

    const int garow = m0 + arow;
    for (int k0 = 0; k0 < DD; k0 += 8) {
        float4 av = make_float4(0.f, 0.f, 0.f, 0.f);
        if (garow < NN) av = *(const float4*)&A[(size_t)garow * DD + k0 + acol];
        As[acol + 0][arow] = fsafe(av.x);
        As[acol + 1][arow] = fsafe(av.y);
        As[acol + 2][arow] = fsafe(av.z);
        As[acol + 3][arow] = fsafe(av.w);
        float4 bv = *(const float4*)&W[(size_t)(k0 + brow) * DD + n0 + bcol];
        *(float4*)&Bs[brow][bcol] = bv;
        __syncthreads();
#pragma unroll
        for (int k = 0; k < 8; k++) {
            float ar[8], br[8];
#pragma unroll
            for (int i = 0; i < 8; i++) ar[i] = As[k][ty * 8 + i];
#pragma unroll
            for (int j = 0; j < 8; j++) br[j] = Bs[k][tx * 8 + j];
#pragma unroll
            for (int i = 0; i < 8; i++)
#pragma unroll
                for (int j = 0; j < 8; j++) acc[i][j] += ar[i] * br[j];
        }
        __syncthreads();
    }
#pragma unroll
    for (int i = 0; i < 8; i++) {
        int r = m0 + ty * 8 + i;
        if (r < NN) {
#pragma unroll
            for (int j = 0; j < 8; j += 4) {
                float4 v = make_float4(acc[i][j], acc[i][j + 1], acc[i][j + 2], acc[i][j + 3]);
                *(float4*)&g_xw[(size_t)r * DD + n0 + tx * 8 + j] = v;
            }
        }
    }
}

// ---------------- fused CSR aggregate + self-loop + bias + LN + relu + residual ----
// One warp per destination node.
__global__ void agg_post_kernel(const float* __restrict__ bias, const float* __restrict__ gam,
                                const float* __restrict__ bet,
                                const float* __restrict__ hres_ext, int res_from_h,
                                float* __restrict__ out_ext, int out_to_h) {
    int node = (int)(((size_t)blockIdx.x * blockDim.x + threadIdx.x) >> 5);
    int lane = threadIdx.x & 31;
    if (node >= NN) return;
    const float* hres = res_from_h ? g_h : hres_ext;
    float* out = out_to_h ? g_h : out_ext;

    int beg = g_off[node];
    int end = beg + g_cnt[node];

    float4 acc0 = make_float4(0.f, 0.f, 0.f, 0.f);
    float4 acc1 = make_float4(0.f, 0.f, 0.f, 0.f);

    int j = beg;
    // 2-way unrolled gather for MLP
    for (; j + 1 < end; j += 2) {
        int ra = __ldg(&g_esrc[j]),     rb = __ldg(&g_esrc[j + 1]);
        float na = __ldg(&g_enrm[j]),   nb = __ldg(&g_enrm[j + 1]);
        const float4* sa = (const float4*)(g_xw + (size_t)ra * DD);
        const float4* sb = (const float4*)(g_xw + (size_t)rb * DD);
        float4 a0 = __ldg(&sa[lane]), a1 = __ldg(&sa[lane + 32]);
        float4 b0 = __ldg(&sb[lane]), b1 = __ldg(&sb[lane + 32]);
        acc0.x += na * a0.x + nb * b0.x; acc0.y += na * a0.y + nb * b0.y;
        acc0.z += na * a0.z + nb * b0.z; acc0.w += na * a0.w + nb * b0.w;
        acc1.x += na * a1.x + nb * b1.x; acc1.y += na * a1.y + nb * b1.y;
        acc1.z += na * a1.z + nb * b1.z; acc1.w += na * a1.w + nb * b1.w;
    }
    if (j < end) {
        int ra = __ldg(&g_esrc[j]);
        float na = __ldg(&g_enrm[j]);
        const float4* sa = (const float4*)(g_xw + (size_t)ra * DD);
        float4 a0 = __ldg(&sa[lane]), a1 = __ldg(&sa[lane + 32]);
        acc0.x += na * a0.x; acc0.y += na * a0.y; acc0.z += na * a0.z; acc0.w += na * a0.w;
        acc1.x += na * a1.x; acc1.y += na * a1.y; acc1.z += na * a1.z; acc1.w += na * a1.w;
    }

    // self loop
    float s2 = g_dis[node]; s2 = s2 * s2;
    const float4* sf = (const float4*)(g_xw + (size_t)node * DD);
    float4 f0 = sf[lane], f1 = sf[lane + 32];
    acc0.x += s2 * f0.x; acc0.y += s2 * f0.y; acc0.z += s2 * f0.z; acc0.w += s2 * f0.w;
    acc1.x += s2 * f1.x; acc1.y += s2 * f1.y; acc1.z += s2 * f1.z; acc1.w += s2 * f1.w;

    // + bias, safe
    float4 bi0 = ((const float4*)bias)[lane], bi1 = ((const float4*)bias)[lane + 32];
    float v[8];
    v[0] = fsafe(acc0.x + bi0.x); v[1] = fsafe(acc0.y + bi0.y);
    v[2] = fsafe(acc0.z + bi0.z); v[3] = fsafe(acc0.w + bi0.w);
    v[4] = fsafe(acc1.x + bi1.x); v[5] = fsafe(acc1.y + bi1.y);
    v[6] = fsafe(acc1.z + bi1.z); v[7] = fsafe(acc1.w + bi1.w);

    // LayerNorm over 256 (8 per lane)
    float s = 0.f;
#pragma unroll
    for (int i = 0; i < 8; i++) s += v[i];
#pragma unroll
    for (int o = 16; o; o >>= 1) s += __shfl_xor_sync(0xffffffffu, s, o);
    float mu = s * (1.0f / DD);

    float vs = 0.f;
#pragma unroll
    for (int i = 0; i < 8; i++) { float d = v[i] - mu; vs += d * d; }
#pragma unroll
    for (int o = 16; o; o >>= 1) vs += __shfl_xor_sync(0xffffffffu, vs, o);
    float inv = rsqrtf(vs * (1.0f / DD) + LN_EPS);

    float4 g0 = ((const float4*)gam)[lane], g1 = ((const float4*)gam)[lane + 32];
    float4 e0 = ((const float4*)bet)[lane], e1 = ((const float4*)bet)[lane + 32];
    const float4* hr = (const float4*)(hres + (size_t)node * DD);
    float4 h0 = hr[lane], h1 = hr[lane + 32];

    float gg[8] = {g0.x, g0.y, g0.z, g0.w, g1.x, g1.y, g1.z, g1.w};
    float bb[8] = {e0.x, e0.y, e0.z, e0.w, e1.x, e1.y, e1.z, e1.w};
    float hh[8] = {h0.x, h0.y, h0.z, h0.w, h1.x, h1.y, h1.z, h1.w};

    float o_[8];
#pragma unroll
    for (int i = 0; i < 8; i++) {
        float y = (v[i] - mu) * inv * gg[i] + bb[i];
        y = fmaxf(fsafe(y), 0.0f);
        o_[i] = fsafe(y + fsafe(hh[i]));
    }
    float4* op = (float4*)(out + (size_t)node * DD);
    op[lane]      = make_float4(o_[0], o_[1], o_[2], o_[3]);
    op[lane + 32] = make_float4(o_[4], o_[5], o_[6], o_[7]);
}

// ---------------- launch ----------------
extern "C" void kernel_launch(void* const* d_in, const int* in_sizes, int n_in,
                              void* d_out, int out_size) {
    const float* x   = (const float*)d_in[0];
    const void*  ei  = d_in[1];
    const float* ew  = (const float*)d_in[2];
    const float* W1  = (const float*)d_in[3];
    const float* b1  = (const float*)d_in[4];
    const float* g1  = (const float*)d_in[5];
    const float* be1 = (const float*)d_in[6];
    const float* W2  = (const float*)d_in[7];
    const float* b2  = (const float*)d_in[8];
    const float* g2  = (const float*)d_in[9];
    const float* be2 = (const float*)d_in[10];
    float* out = (float*)d_out;

    detect_idx_kernel<<<1, 32>>>(ei);

    // CSR build (shared by both layers)
    zero_kernel<<<(NN + 255) / 256, 256>>>();
    count_kernel<<<(EE + 255) / 256, 256>>>(ei, ew);
    dis_kernel<<<(NN + 255) / 256, 256>>>();
    scan1_kernel<<<NB, SCAN_B>>>();
    scan2_kernel<<<1, 32>>>();
    scan3_kernel<<<NB, SCAN_B>>>();
    fill_kernel<<<(EE + 255) / 256, 256>>>(ei, ew);

    dim3 gemm_grid(DD / 128, (NN + 127) / 128);
    int agg_blocks = (int)(((size_t)NN * 32 + 255) / 256);

    // ---- layer 1 ----
    sgemm_kernel<<<gemm_grid, 256>>>(x, 0, W1);
    agg_post_kernel<<<agg_blocks, 256>>>(b1, g1, be1, x, 0, nullptr, 1);   // -> g_h

    // ---- layer 2 ----
    sgemm_kernel<<<gemm_grid, 256>>>(nullptr, 1, W2);
    agg_post_kernel<<<agg_blocks, 256>>>(b2, g2, be2, nullptr, 1, out, 0); // -> d_out
}

// round 3
// speedup vs baseline: 3.1586x; 1.7580x over previous
#include <cuda_runtime.h>
#include <cuda_fp16.h>
#include <math.h>

#define NN 100000
#define EE 3200000
#define DD 256
#define LN_EPS 1e-5f
#define SCAN_B 1024
#define NB ((NN + SCAN_B - 1) / SCAN_B)

// ---------------- scratch (static device globals: no allocation) ----------------
__device__ float  g_h[(size_t)NN * DD];     // layer-1 output (fp32)
__device__ __half g_xw16[(size_t)NN * DD];  // h @ W in fp16 (for gather)
__device__ float  g_deg[NN];
__device__ float  g_dis[NN];
__device__ int    g_cnt[NN];
__device__ int    g_off[NN];
__device__ int    g_cur[NN];
__device__ int    g_bsum[NB];
__device__ int    g_esrc[EE];
__device__ float  g_enrm[EE];
__device__ __half g_wt_hi[2][DD * DD];      // W^T hi (n-major)
__device__ __half g_wt_lo[2][DD * DD];      // W^T lo
__device__ int    g_idx64;

__device__ __forceinline__ float fsafe(float v) { return isfinite(v) ? v : 0.0f; }

__device__ __forceinline__ int load_idx(const void* base, long long e) {
    if (g_idx64) return (int)((const long long*)base)[e];
    return ((const int*)base)[e];
}

// ---------------- edge-index dtype detection ----------------
__global__ void detect_idx_kernel(const void* ei) {
    if (threadIdx.x == 0 && blockIdx.x == 0) {
        const long long* p = (const long long*)ei;
        int ok64 = 1;
        for (int i = 0; i < 1024; i++) {
            long long v = p[i];
            if (v < 0 || v >= NN) { ok64 = 0; break; }
        }
        g_idx64 = ok64;
    }
}

// ---------------- CSR build ----------------
__global__ void zero_kernel() {
    int i = blockIdx.x * blockDim.x + threadIdx.x;
    if (i < NN) { g_deg[i] = 0.0f; g_cnt[i] = 0; }
}

__global__ void count_kernel(const void* __restrict__ ei, const float* __restrict__ ew) {
    int e = blockIdx.x * blockDim.x + threadIdx.x;
    if (e < EE) {
        float w = fmaxf(fabsf(fsafe(ew[e])), 1e-6f);
        int c = load_idx(ei, (long long)EE + e);
        atomicAdd(&g_deg[c], w);
        atomicAdd(&g_cnt[c], 1);
    }
}

__global__ void dis_kernel() {
    int i = blockIdx.x * blockDim.x + threadIdx.x;
    if (i < NN) g_dis[i] = rsqrtf(g_deg[i] + 1.0f);
}

__global__ void scan1_kernel() {
    __shared__ int s[SCAN_B];
    int tid = threadIdx.x;
    int i = blockIdx.x * SCAN_B + tid;
    int v = (i < NN) ? g_cnt[i] : 0;
    s[tid] = v;
    __syncthreads();
#pragma unroll
    for (int o = 1; o < SCAN_B; o <<= 1) {
        int t = (tid >= o) ? s[tid - o] : 0;
        __syncthreads();
        s[tid] += t;
        __syncthreads();
    }
    if (i < NN) g_off[i] = s[tid] - v;
    if (tid == SCAN_B - 1) g_bsum[blockIdx.x] = s[tid];
}

__global__ void scan2_kernel() {
    if (threadIdx.x == 0 && blockIdx.x == 0) {
        int run = 0;
        for (int b = 0; b < NB; b++) { int t = g_bsum[b]; g_bsum[b] = run; run += t; }
    }
}

__global__ void scan3_kernel() {
    int i = blockIdx.x * SCAN_B + threadIdx.x;
    if (i < NN) {
        int o = g_off[i] + g_bsum[blockIdx.x];
        g_off[i] = o;
        g_cur[i] = o;
    }
}

__global__ void fill_kernel(const void* __restrict__ ei, const float* __restrict__ ew) {
    int e = blockIdx.x * blockDim.x + threadIdx.x;
    if (e < EE) {
        int r = load_idx(ei, e);
        int c = load_idx(ei, (long long)EE + e);
        float w = fmaxf(fabsf(fsafe(ew[e])), 1e-6f);
        float norm = g_dis[r] * w * g_dis[c];
        int pos = atomicAdd(&g_cur[c], 1);
        g_esrc[pos] = r;
        g_enrm[pos] = norm;
    }
}

// ---------------- W transpose + hi/lo split ----------------
__global__ void wsplit_kernel(const float* __restrict__ W, int which) {
    int idx = blockIdx.x * blockDim.x + threadIdx.x;
    if (idx >= DD * DD) return;
    int k = idx >> 8, n = idx & 255;
    float v = W[idx];                  // W[k][n]
    __half h = __float2half_rn(v);
    float lo = v - __half2float(h);
    g_wt_hi[which][n * DD + k] = h;
    g_wt_lo[which][n * DD + k] = __float2half_rn(lo);
}

// ---------------- HMMA GEMM: g_xw16 = fp16( safe(A) @ W ) ----------------
// Block tile 128(M) x 128(N), 256 threads = 8 warps (2m x 4n), warp tile 64x32.
// Split-fp16: 3 MMAs per fragment pair (hi*hi + hi*lo + lo*hi) -> near-fp32.
#define MMA_OP(d, a, b0, b1)                                                        \
    asm volatile("mma.sync.aligned.m16n8k16.row.col.f32.f16.f16.f32 "               \
                 "{%0,%1,%2,%3}, {%4,%5,%6,%7}, {%8,%9}, {%0,%1,%2,%3};"            \
                 : "+f"(d[0]), "+f"(d[1]), "+f"(d[2]), "+f"(d[3])                   \
                 : "r"(a[0]), "r"(a[1]), "r"(a[2]), "r"(a[3]), "r"(b0), "r"(b1))

__global__ void hgemm_kernel(const float* __restrict__ Aext, int a_from_h, int which) {
    __shared__ __align__(16) __half As_hi[128][16];
    __shared__ __align__(16) __half As_lo[128][16];
    __shared__ __align__(16) __half Bs_hi[128][16];
    __shared__ __align__(16) __half Bs_lo[128][16];
    const float* A = a_from_h ? g_h : Aext;

    const int tid = threadIdx.x;
    const int m0 = blockIdx.y * 128;
    const int n0 = blockIdx.x * 128;
    const int lane = tid & 31, wid = tid >> 5;
    const int wm = (wid >> 2) * 64;   // warp m offset (0/64)
    const int wn = (wid & 3) * 32;    // warp n offset (0..96)
    const int g = lane >> 2, tg = lane & 3;

    float acc[4][4][4];
#pragma unroll
    for (int i = 0; i < 4; i++)
#pragma unroll
        for (int j = 0; j < 4; j++)
#pragma unroll
            for (int q = 0; q < 4; q++) acc[i][j][q] = 0.0f;

    const int arow = tid >> 1;            // 0..127
    const int kseg = (tid & 1) * 8;       // 0 or 8
    const int garow = m0 + arow;
    const bool aval = garow < NN;
    const __half* wh = g_wt_hi[which];
    const __half* wl = g_wt_lo[which];
    const int gbn = n0 + arow;            // global n for B load (row of W^T)

    for (int k0 = 0; k0 < DD; k0 += 16) {
        // --- load + split A slab (128x16) ---
        float4 v0 = make_float4(0.f, 0.f, 0.f, 0.f), v1 = v0;
        if (aval) {
            v0 = *(const float4*)&A[(size_t)garow * DD + k0 + kseg];
            v1 = *(const float4*)&A[(size_t)garow * DD + k0 + kseg + 4];
        }
        float f[8] = {fsafe(v0.x), fsafe(v0.y), fsafe(v0.z), fsafe(v0.w),
                      fsafe(v1.x), fsafe(v1.y), fsafe(v1.z), fsafe(v1.w)};
        __half2 ph[4], pl[4];
#pragma unroll
        for (int q = 0; q < 4; q++) {
            __half h0 = __float2half_rn(f[2 * q]);
            __half h1 = __float2half_rn(f[2 * q + 1]);
            ph[q] = __halves2half2(h0, h1);
            pl[q] = __halves2half2(__float2half_rn(f[2 * q] - __half2float(h0)),
                                   __float2half_rn(f[2 * q + 1] - __half2float(h1)));
        }
        *(uint4*)&As_hi[arow][kseg] = *(uint4*)ph;
        *(uint4*)&As_lo[arow][kseg] = *(uint4*)pl;
        // --- load B slab (128 n-rows x 16 k), already split fp16 ---
        *(uint4*)&Bs_hi[arow][kseg] = *(const uint4*)&wh[(size_t)gbn * DD + k0 + kseg];
        *(uint4*)&Bs_lo[arow][kseg] = *(const uint4*)&wl[(size_t)gbn * DD + k0 + kseg];
        __syncthreads();

        // --- fragments + MMA ---
        unsigned ah[4][4], al[4][4];
#pragma unroll
        for (int i = 0; i < 4; i++) {
            int r = wm + i * 16 + g;
            ah[i][0] = *(const unsigned*)&As_hi[r][2 * tg];
            ah[i][1] = *(const unsigned*)&As_hi[r + 8][2 * tg];
            ah[i][2] = *(const unsigned*)&As_hi[r][2 * tg + 8];
            ah[i][3] = *(const unsigned*)&As_hi[r + 8][2 * tg + 8];
            al[i][0] = *(const unsigned*)&As_lo[r][2 * tg];
            al[i][1] = *(const unsigned*)&As_lo[r + 8][2 * tg];
            al[i][2] = *(const unsigned*)&As_lo[r][2 * tg + 8];
            al[i][3] = *(const unsigned*)&As_lo[r + 8][2 * tg + 8];
        }
#pragma unroll
        for (int j = 0; j < 4; j++) {
            int c = wn + j * 8 + g;
            unsigned bh0 = *(const unsigned*)&Bs_hi[c][2 * tg];
            unsigned bh1 = *(const unsigned*)&Bs_hi[c][2 * tg + 8];
            unsigned bl0 = *(const unsigned*)&Bs_lo[c][2 * tg];
            unsigned bl1 = *(const unsigned*)&Bs_lo[c][2 * tg + 8];
#pragma unroll
            for (int i = 0; i < 4; i++) {
                MMA_OP(acc[i][j], ah[i], bh0, bh1);
                MMA_OP(acc[i][j], ah[i], bl0, bl1);
                MMA_OP(acc[i][j], al[i], bh0, bh1);
            }
        }
        __syncthreads();
    }

    // --- epilogue: write fp16 xw ---
#pragma unroll
    for (int i = 0; i < 4; i++) {
        int r0 = m0 + wm + i * 16 + g;
        int r1 = r0 + 8;
#pragma unroll
        for (int j = 0; j < 4; j++) {
            int c = n0 + wn + j * 8 + 2 * tg;
            if (r0 < NN)
                *(__half2*)&g_xw16[(size_t)r0 * DD + c] =
                    __floats2half2_rn(acc[i][j][0], acc[i][j][1]);
            if (r1 < NN)
                *(__half2*)&g_xw16[(size_t)r1 * DD + c] =
                    __floats2half2_rn(acc[i][j][2], acc[i][j][3]);
        }
    }
}

// ---------------- fused CSR aggregate + self-loop + bias + LN + relu + residual ----
// One warp per destination node; lane owns cols lane*8 .. lane*8+7.
__global__ void agg_post_kernel(const float* __restrict__ bias, const float* __restrict__ gam,
                                const float* __restrict__ bet,
                                const float* __restrict__ hres_ext, int res_from_h,
                                float* __restrict__ out_ext, int out_to_h) {
    int node = (int)(((size_t)blockIdx.x * blockDim.x + threadIdx.x) >> 5);
    int lane = threadIdx.x & 31;
    if (node >= NN) return;
    const float* hres = res_from_h ? g_h : hres_ext;
    float* out = out_to_h ? g_h : out_ext;

    int beg = g_off[node];
    int end = beg + g_cnt[node];

    float acc[8];
#pragma unroll
    for (int i = 0; i < 8; i++) acc[i] = 0.0f;

    int j = beg;
    for (; j + 1 < end; j += 2) {
        int ra = __ldg(&g_esrc[j]), rb = __ldg(&g_esrc[j + 1]);
        float na = __ldg(&g_enrm[j]), nb = __ldg(&g_enrm[j + 1]);
        uint4 rwa = *(const uint4*)(g_xw16 + (size_t)ra * DD + lane * 8);
        uint4 rwb = *(const uint4*)(g_xw16 + (size_t)rb * DD + lane * 8);
        const __half2* pa = (const __half2*)&rwa;
        const __half2* pb = (const __half2*)&rwb;
#pragma unroll
        for (int q = 0; q < 4; q++) {
            float2 fa = __half22float2(pa[q]);
            float2 fb = __half22float2(pb[q]);
            acc[2 * q]     += na * fa.x + nb * fb.x;
            acc[2 * q + 1] += na * fa.y + nb * fb.y;
        }
    }
    if (j < end) {
        int ra = __ldg(&g_esrc[j]);
        float na = __ldg(&g_enrm[j]);
        uint4 rwa = *(const uint4*)(g_xw16 + (size_t)ra * DD + lane * 8);
        const __half2* pa = (const __half2*)&rwa;
#pragma unroll
        for (int q = 0; q < 4; q++) {
            float2 fa = __half22float2(pa[q]);
            acc[2 * q]     += na * fa.x;
            acc[2 * q + 1] += na * fa.y;
        }
    }

    // self loop
    {
        float s2 = g_dis[node]; s2 = s2 * s2;
        uint4 rw = *(const uint4*)(g_xw16 + (size_t)node * DD + lane * 8);
        const __half2* ps = (const __half2*)&rw;
#pragma unroll
        for (int q = 0; q < 4; q++) {
            float2 fs = __half22float2(ps[q]);
            acc[2 * q]     += s2 * fs.x;
            acc[2 * q + 1] += s2 * fs.y;
        }
    }

    // + bias, safe
    float4 bi0 = ((const float4*)bias)[2 * lane], bi1 = ((const float4*)bias)[2 * lane + 1];
    float v[8];
    v[0] = fsafe(acc[0] + bi0.x); v[1] = fsafe(acc[1] + bi0.y);
    v[2] = fsafe(acc[2] + bi0.z); v[3] = fsafe(acc[3] + bi0.w);
    v[4] = fsafe(acc[4] + bi1.x); v[5] = fsafe(acc[5] + bi1.y);
    v[6] = fsafe(acc[6] + bi1.z); v[7] = fsafe(acc[7] + bi1.w);

    // LayerNorm over 256
    float s = 0.f;
#pragma unroll
    for (int i = 0; i < 8; i++) s += v[i];
#pragma unroll
    for (int o = 16; o; o >>= 1) s += __shfl_xor_sync(0xffffffffu, s, o);
    float mu = s * (1.0f / DD);

    float vs = 0.f;
#pragma unroll
    for (int i = 0; i < 8; i++) { float d = v[i] - mu; vs += d * d; }
#pragma unroll
    for (int o = 16; o; o >>= 1) vs += __shfl_xor_sync(0xffffffffu, vs, o);
    float inv = rsqrtf(vs * (1.0f / DD) + LN_EPS);

    float4 g0 = ((const float4*)gam)[2 * lane], g1 = ((const float4*)gam)[2 * lane + 1];
    float4 e0 = ((const float4*)bet)[2 * lane], e1 = ((const float4*)bet)[2 * lane + 1];
    const float4* hr = (const float4*)(hres + (size_t)node * DD);
    float4 h0 = hr[2 * lane], h1 = hr[2 * lane + 1];

    float gg[8] = {g0.x, g0.y, g0.z, g0.w, g1.x, g1.y, g1.z, g1.w};
    float bb[8] = {e0.x, e0.y, e0.z, e0.w, e1.x, e1.y, e1.z, e1.w};
    float hh[8] = {h0.x, h0.y, h0.z, h0.w, h1.x, h1.y, h1.z, h1.w};

    float o_[8];
#pragma unroll
    for (int i = 0; i < 8; i++) {
        float y = (v[i] - mu) * inv * gg[i] + bb[i];
        y = fmaxf(fsafe(y), 0.0f);
        o_[i] = fsafe(y + fsafe(hh[i]));
    }
    float4* op = (float4*)(out + (size_t)node * DD);
    op[2 * lane]     = make_float4(o_[0], o_[1], o_[2], o_[3]);
    op[2 * lane + 1] = make_float4(o_[4], o_[5], o_[6], o_[7]);
}

// ---------------- launch ----------------
extern "C" void kernel_launch(void* const* d_in, const int* in_sizes, int n_in,
                              void* d_out, int out_size) {
    const float* x   = (const float*)d_in[0];
    const void*  ei  = d_in[1];
    const float* ew  = (const float*)d_in[2];
    const float* W1  = (const float*)d_in[3];
    const float* b1  = (const float*)d_in[4];
    const float* g1  = (const float*)d_in[5];
    const float* be1 = (const float*)d_in[6];
    const float* W2  = (const float*)d_in[7];
    const float* b2  = (const float*)d_in[8];
    const float* g2  = (const float*)d_in[9];
    const float* be2 = (const float*)d_in[10];
    float* out = (float*)d_out;

    detect_idx_kernel<<<1, 32>>>(ei);

    // CSR build (shared by both layers)
    zero_kernel<<<(NN + 255) / 256, 256>>>();
    count_kernel<<<(EE + 255) / 256, 256>>>(ei, ew);
    dis_kernel<<<(NN + 255) / 256, 256>>>();
    scan1_kernel<<<NB, SCAN_B>>>();
    scan2_kernel<<<1, 32>>>();
    scan3_kernel<<<NB, SCAN_B>>>();
    fill_kernel<<<(EE + 255) / 256, 256>>>(ei, ew);

    // W split (both layers)
    wsplit_kernel<<<(DD * DD + 255) / 256, 256>>>(W1, 0);
    wsplit_kernel<<<(DD * DD + 255) / 256, 256>>>(W2, 1);

    dim3 gemm_grid(DD / 128, (NN + 127) / 128);
    int agg_blocks = (int)(((size_t)NN * 32 + 255) / 256);

    // ---- layer 1 ----
    hgemm_kernel<<<gemm_grid, 256>>>(x, 0, 0);
    agg_post_kernel<<<agg_blocks, 256>>>(b1, g1, be1, x, 0, nullptr, 1);   // -> g_h

    // ---- layer 2 ----
    hgemm_kernel<<<gemm_grid, 256>>>(nullptr, 1, 1);
    agg_post_kernel<<<agg_blocks, 256>>>(b2, g2, be2, nullptr, 1, out, 0); // -> d_out
}